// round 16
// baseline (speedup 1.0000x reference)
#include <cuda_runtime.h>

#define BB 16
#define SS 4096
#define HH 1024

// scratch: per-segment partial dec_fea [4][B][H]
__device__ float g_part[4 * BB * HH];

__device__ __forceinline__ float tanh_fast(float x) {
    float y;
    asm("tanh.approx.f32 %0, %1;" : "=f"(y) : "f"(x));
    return y;
}

// streaming (evict-first) float4 load for zero-reuse tensors
__device__ __forceinline__ float4 ldcs4(const float4* p) {
    float4 r;
    asm("ld.global.cs.v4.f32 {%0,%1,%2,%3}, [%4];"
        : "=f"(r.x), "=f"(r.y), "=f"(r.z), "=f"(r.w) : "l"(p));
    return r;
}

// streaming store for write-once data
__device__ __forceinline__ void stcs4(float4* p, float4 v) {
    asm volatile("st.global.cs.v4.f32 [%0], {%1,%2,%3,%4};"
                 :: "l"(p), "f"(v.x), "f"(v.y), "f"(v.z), "f"(v.w) : "memory");
}

__device__ __forceinline__ float warp_sum(float v) {
#pragma unroll
    for (int o = 16; o > 0; o >>= 1) v += __shfl_xor_sync(0xffffffffu, v, o);
    return v;
}

__device__ __forceinline__ float warp_max(float v) {
#pragma unroll
    for (int o = 16; o > 0; o >>= 1) v = fmaxf(v, __shfl_xor_sync(0xffffffffu, v, o));
    return v;
}

// ---------------------------------------------------------------------------
// K1: split-K decode projection, 4 segments of 256 floats.
// grid (256, 4) x 128 thr. Warp = (h, seg); merged butterfly-16 (5 SHFL).
// Even lane l writes batch (l>>1)&15. Bias in seg 0. Also zeroes scores.
// ---------------------------------------------------------------------------
__global__ void k_decproj(const float* __restrict__ s_t,
                          const float* __restrict__ W,
                          const float* __restrict__ bias,
                          float* __restrict__ scores) {
    int gid = (blockIdx.x * 4 + blockIdx.y) * 128 + threadIdx.x;
    if (gid < 65536) scores[gid] = 0.f;

    int warp = threadIdx.x >> 5, lane = threadIdx.x & 31;
    int h   = blockIdx.x * 4 + warp;
    int seg = blockIdx.y;
    int k4a = seg * 64 + lane;
    int k4b = k4a + 32;

    const float4* Wrow = reinterpret_cast<const float4*>(W + (size_t)h * HH);
    float4 wa = __ldg(Wrow + k4a);
    float4 wb = __ldg(Wrow + k4b);

    float r[16];
#pragma unroll
    for (int b = 0; b < BB; b++) {
        const float4* sb = reinterpret_cast<const float4*>(s_t + b * HH);
        float4 sa = __ldg(sb + k4a);
        float4 s2 = __ldg(sb + k4b);
        r[b] = (wa.x * sa.x + wa.y * sa.y) + (wa.z * sa.z + wa.w * sa.w)
             + (wb.x * s2.x + wb.y * s2.y) + (wb.z * s2.z + wb.w * s2.w);
    }

    float m8[8];
#pragma unroll
    for (int i = 0; i < 8; i++) {
        bool hi = (lane & 16) != 0;
        float keep = hi ? r[i + 8] : r[i];
        float send = hi ? r[i] : r[i + 8];
        m8[i] = keep + __shfl_xor_sync(0xffffffffu, send, 16);
    }
    float m4[4];
#pragma unroll
    for (int i = 0; i < 4; i++) {
        bool hi = (lane & 8) != 0;
        float keep = hi ? m8[i + 4] : m8[i];
        float send = hi ? m8[i] : m8[i + 4];
        m4[i] = keep + __shfl_xor_sync(0xffffffffu, send, 8);
    }
    float m2[2];
#pragma unroll
    for (int i = 0; i < 2; i++) {
        bool hi = (lane & 4) != 0;
        float keep = hi ? m4[i + 2] : m4[i];
        float send = hi ? m4[i] : m4[i + 2];
        m2[i] = keep + __shfl_xor_sync(0xffffffffu, send, 4);
    }
    float m1;
    {
        bool hi = (lane & 2) != 0;
        float keep = hi ? m2[1] : m2[0];
        float send = hi ? m2[0] : m2[1];
        m1 = keep + __shfl_xor_sync(0xffffffffu, send, 2);
    }
    m1 += __shfl_xor_sync(0xffffffffu, m1, 1);

    if ((lane & 1) == 0) {
        int b = (lane >> 1) & 15;
        float bi = (seg == 0) ? __ldg(bias + h) : 0.f;
        g_part[(seg * BB + b) * HH + h] = m1 + bi;
    }
}

// ---------------------------------------------------------------------------
// K2: scores[b][s] += sum_{h in slice} tanh(ef + dec + cov*Wc) * v
// Flat 8-row .cs LDG batch (MLP 8), merged butterflies + REDG.
// ---------------------------------------------------------------------------
#define SC_CHUNK 64

__device__ __forceinline__ void butterfly4_atomic(float a0, float a1, float a2,
                                                  float a3, int lane,
                                                  float* dst) {
    float x01 = (lane & 16) ? a1 : a0;
    float y01 = (lane & 16) ? a0 : a1;
    x01 += __shfl_xor_sync(0xffffffffu, y01, 16);
    float x23 = (lane & 16) ? a3 : a2;
    float y23 = (lane & 16) ? a2 : a3;
    x23 += __shfl_xor_sync(0xffffffffu, y23, 16);
    float m0 = (lane & 8) ? x23 : x01;
    float m1 = (lane & 8) ? x01 : x23;
    m0 += __shfl_xor_sync(0xffffffffu, m1, 8);
    m0 += __shfl_xor_sync(0xffffffffu, m0, 4);
    m0 += __shfl_xor_sync(0xffffffffu, m0, 2);
    m0 += __shfl_xor_sync(0xffffffffu, m0, 1);
    if ((lane & 7) == 0) {
        int r = ((lane >> 4) & 1) | ((lane >> 2) & 2);
        atomicAdd(dst + r, m0);
    }
}

__global__ void __launch_bounds__(128, 8) k_scores(const float* __restrict__ ef,
                                                   const float* __restrict__ cov,
                                                   const float* __restrict__ Wc,
                                                   const float* __restrict__ v,
                                                   float* __restrict__ scores) {
    int b  = blockIdx.y;
    int s0 = blockIdx.x * SC_CHUNK;
    int t  = blockIdx.z * 128 + threadIdx.x;
    int lane = threadIdx.x & 31;

    float4 p0 = __ldg(reinterpret_cast<const float4*>(g_part + (0 * BB + b) * HH) + t);
    float4 p1 = __ldg(reinterpret_cast<const float4*>(g_part + (1 * BB + b) * HH) + t);
    float4 p2 = __ldg(reinterpret_cast<const float4*>(g_part + (2 * BB + b) * HH) + t);
    float4 p3 = __ldg(reinterpret_cast<const float4*>(g_part + (3 * BB + b) * HH) + t);
    float4 d4;
    d4.x = (p0.x + p1.x) + (p2.x + p3.x);
    d4.y = (p0.y + p1.y) + (p2.y + p3.y);
    d4.z = (p0.z + p1.z) + (p2.z + p3.z);
    d4.w = (p0.w + p1.w) + (p2.w + p3.w);
    float4 w4 = __ldg(reinterpret_cast<const float4*>(Wc) + t);
    float4 v4 = __ldg(reinterpret_cast<const float4*>(v) + t);

    const float4* efb  = reinterpret_cast<const float4*>(ef + ((size_t)b * SS) * HH);
    const float4* cov4 = reinterpret_cast<const float4*>(cov + b * SS + s0);
    float* sc = scores + b * SS + s0;

#pragma unroll 1
    for (int g = 0; g < SC_CHUNK / 8; g++) {
        float4 f[8];
#pragma unroll
        for (int r = 0; r < 8; r++)
            f[r] = ldcs4(efb + (size_t)(s0 + g * 8 + r) * (HH / 4) + t);
        float4 c4a = __ldg(cov4 + g * 2);
        float4 c4b = __ldg(cov4 + g * 2 + 1);

        const float cr[8] = {c4a.x, c4a.y, c4a.z, c4a.w,
                             c4b.x, c4b.y, c4b.z, c4b.w};
        float acc[8];
#pragma unroll
        for (int r = 0; r < 8; r++) {
            float c = cr[r];
            float e0 = tanh_fast(f[r].x + fmaf(c, w4.x, d4.x));
            float e1 = tanh_fast(f[r].y + fmaf(c, w4.y, d4.y));
            float e2 = tanh_fast(f[r].z + fmaf(c, w4.z, d4.z));
            float e3 = tanh_fast(f[r].w + fmaf(c, w4.w, d4.w));
            acc[r] = fmaf(e0, v4.x, fmaf(e1, v4.y, fmaf(e2, v4.z, e3 * v4.w)));
        }
        butterfly4_atomic(acc[0], acc[1], acc[2], acc[3], lane, sc + g * 8);
        butterfly4_atomic(acc[4], acc[5], acc[6], acc[7], lane, sc + g * 8 + 4);
    }
}

// ---------------------------------------------------------------------------
// K3: masked softmax + renorm, 4 blocks per batch (grid BB x 4, 256 thr).
// Each block redundantly computes stats, writes its quarter of attn1/attn2
// (attn2 via streaming store; never re-read), zeroes its quarter of c_t.
// ---------------------------------------------------------------------------
__global__ void __launch_bounds__(256) k_softmax(const float* __restrict__ mask,
                                                 float* __restrict__ out) {
    int b   = blockIdx.x;
    int q   = blockIdx.y;
    int tid = threadIdx.x;
    int warp = tid >> 5, lane = tid & 31;

    const float4* scb = reinterpret_cast<const float4*>(out + BB * HH + 2 * BB * SS + b * SS);
    const float4* mb  = reinterpret_cast<const float4*>(mask + b * SS);

    __shared__ float red[8];

    float4 sv[4];
#pragma unroll
    for (int k = 0; k < 4; k++) sv[k] = __ldg(scb + tid + k * 256);

    float mx = -3.402823466e+38f;
#pragma unroll
    for (int k = 0; k < 4; k++)
        mx = fmaxf(mx, fmaxf(fmaxf(sv[k].x, sv[k].y), fmaxf(sv[k].z, sv[k].w)));
    mx = warp_max(mx);
    if (lane == 0) red[warp] = mx;
    __syncthreads();
    if (tid == 0) {
        float t = red[0];
#pragma unroll
        for (int i = 1; i < 8; i++) t = fmaxf(t, red[i]);
        red[0] = t;
    }
    __syncthreads();
    mx = red[0];
    __syncthreads();

    float lsum = 0.f;
#pragma unroll
    for (int k = 0; k < 4; k++) {
        sv[k].x = __expf(sv[k].x - mx); sv[k].y = __expf(sv[k].y - mx);
        sv[k].z = __expf(sv[k].z - mx); sv[k].w = __expf(sv[k].w - mx);
        lsum += (sv[k].x + sv[k].y) + (sv[k].z + sv[k].w);
    }
    lsum = warp_sum(lsum);
    if (lane == 0) red[warp] = lsum;
    __syncthreads();
    if (tid == 0) {
        float t = 0.f;
#pragma unroll
        for (int i = 0; i < 8; i++) t += red[i];
        red[0] = t;
    }
    __syncthreads();
    float inv = 1.f / red[0];
    __syncthreads();

    float4 mk[4];
    float lms = 0.f;
#pragma unroll
    for (int k = 0; k < 4; k++) {
        mk[k] = __ldg(mb + tid + k * 256);
        lms += (sv[k].x * mk[k].x + sv[k].y * mk[k].y)
             + (sv[k].z * mk[k].z + sv[k].w * mk[k].w);
    }
    lms = warp_sum(lms);
    if (lane == 0) red[warp] = lms;
    __syncthreads();
    if (tid == 0) {
        float t = 0.f;
#pragma unroll
        for (int i = 0; i < 8; i++) t += red[i];
        red[0] = t;
    }
    __syncthreads();
    float inv2 = 1.f / (red[0] * inv + 1e-20f);
    float scale = inv * inv2;

    float4 a;
    a.x = sv[q].x * mk[q].x * scale; a.y = sv[q].y * mk[q].y * scale;
    a.z = sv[q].z * mk[q].z * scale; a.w = sv[q].w * mk[q].w * scale;
    int o4 = q * 256 + tid;
    reinterpret_cast<float4*>(out + BB * HH + b * SS)[o4] = a;   // attn1 (re-read by K4)
    stcs4(reinterpret_cast<float4*>(out + BB * HH + BB * SS + b * SS) + o4, a);  // attn2

    out[b * HH + q * 256 + tid] = 0.f;
}

// ---------------------------------------------------------------------------
// K4: c_t[b][h] += sum_{s in chunk} attn[b,s] * eo[b,s,h]
// k_scores-style flat 8-deep load batch (MLP 8) + dual accumulator chains.
// launch_bounds(128,8): 8 blocks/SM resident.
// ---------------------------------------------------------------------------
#define K4_CHUNK 64
__global__ void __launch_bounds__(128, 8) k_context(const float* __restrict__ eo,
                                                    float* __restrict__ out) {
    int b  = blockIdx.y;
    int s0 = blockIdx.x * K4_CHUNK;
    int t  = blockIdx.z * 128 + threadIdx.x;
    const float4* attn4 = reinterpret_cast<const float4*>(out + BB * HH + b * SS + s0);
    const float4* eob = reinterpret_cast<const float4*>(eo + ((size_t)b * SS) * HH);

    float4 acc0 = make_float4(0.f, 0.f, 0.f, 0.f);
    float4 acc1 = make_float4(0.f, 0.f, 0.f, 0.f);

#pragma unroll 1
    for (int g = 0; g < K4_CHUNK / 8; g++) {
        // ---- load phase: 8 independent streaming LDG.128 + 2 attn loads ----
        float4 f[8];
#pragma unroll
        for (int r = 0; r < 8; r++)
            f[r] = ldcs4(eob + (size_t)(s0 + g * 8 + r) * (HH / 4) + t);
        float4 a4a = __ldg(attn4 + g * 2);
        float4 a4b = __ldg(attn4 + g * 2 + 1);

        // ---- compute phase: two independent accumulator chains ----
        const float ar[8] = {a4a.x, a4a.y, a4a.z, a4a.w,
                             a4b.x, a4b.y, a4b.z, a4b.w};
#pragma unroll
        for (int r = 0; r < 8; r += 2) {
            acc0.x = fmaf(ar[r], f[r].x, acc0.x);
            acc0.y = fmaf(ar[r], f[r].y, acc0.y);
            acc0.z = fmaf(ar[r], f[r].z, acc0.z);
            acc0.w = fmaf(ar[r], f[r].w, acc0.w);
            acc1.x = fmaf(ar[r + 1], f[r + 1].x, acc1.x);
            acc1.y = fmaf(ar[r + 1], f[r + 1].y, acc1.y);
            acc1.z = fmaf(ar[r + 1], f[r + 1].z, acc1.z);
            acc1.w = fmaf(ar[r + 1], f[r + 1].w, acc1.w);
        }
    }
    float* ct = out + b * HH + t * 4;
    atomicAdd(ct + 0, acc0.x + acc1.x);
    atomicAdd(ct + 1, acc0.y + acc1.y);
    atomicAdd(ct + 2, acc0.z + acc1.z);
    atomicAdd(ct + 3, acc0.w + acc1.w);
}

// ---------------------------------------------------------------------------
extern "C" void kernel_launch(void* const* d_in, const int* in_sizes, int n_in,
                              void* d_out, int out_size) {
    const float* s_t_hat = (const float*)d_in[0];
    const float* enc_out = (const float*)d_in[1];
    const float* enc_fea = (const float*)d_in[2];
    const float* mask    = (const float*)d_in[3];
    const float* cov     = (const float*)d_in[4];
    const float* W_dec   = (const float*)d_in[5];
    const float* b_dec   = (const float*)d_in[6];
    const float* W_c     = (const float*)d_in[7];
    const float* v       = (const float*)d_in[8];
    float* out = (float*)d_out;

    float* scores = out + BB * HH + 2 * BB * SS;

    k_decproj<<<dim3(256, 4), 128>>>(s_t_hat, W_dec, b_dec, scores);
    k_scores<<<dim3(SS / SC_CHUNK, BB, 2), 128>>>(enc_fea, cov, W_c, v, scores);
    k_softmax<<<dim3(BB, 4), 256>>>(mask, out);
    k_context<<<dim3(SS / K4_CHUNK, BB, 2), 128>>>(enc_out, out);
}